// round 1
// baseline (speedup 1.0000x reference)
#include <cuda_runtime.h>
#include <math.h>

// Problem constants
#define Bn 8
#define Ln 4096
#define Hn 1024
#define Nn 32
#define Tn 256          // chunk length
#define Cn 16           // chunks per sequence (Tn*Cn == Ln)
#define NP 16           // mode pairs (Nn/2) for f32x2 packing

typedef unsigned long long ull;

// ---- persistent device scratch / coefficient tables (no allocs allowed) ----
__device__ float4 g_ab[Hn * NP];           // (a_lo, a_hi, b_lo, b_hi) per (h, pair)
__device__ float4 g_pq[Hn * NP];           // (p_lo, p_hi, q_lo, q_hi)
__device__ float4 g_S[Hn * Nn];            // (s_T, beta*s_{T-1}, s_{T-1}, beta*s_{T-2})
__device__ float4 g_state[Bn * Hn * Cn * NP]; // (Y1[2m], Y2[2m], Y1[2m+1], Y2[2m+1])

// ---- packed fp32x2 helpers (Blackwell FFMA2 path, PTX-only) ----
static __device__ __forceinline__ ull pk2(float lo, float hi) {
    ull r;
    asm("mov.b64 %0, {%1, %2};" : "=l"(r)
        : "r"(__float_as_uint(lo)), "r"(__float_as_uint(hi)));
    return r;
}
static __device__ __forceinline__ void upk2(float& lo, float& hi, ull v) {
    unsigned a, b;
    asm("mov.b64 {%0, %1}, %2;" : "=r"(a), "=r"(b) : "l"(v));
    lo = __uint_as_float(a); hi = __uint_as_float(b);
}
static __device__ __forceinline__ ull fma2(ull a, ull b, ull c) {
    ull d;
    asm("fma.rn.f32x2 %0, %1, %2, %3;" : "=l"(d) : "l"(a), "l"(b), "l"(c));
    return d;
}
static __device__ __forceinline__ ull mul2(ull a, ull b) {
    ull d;
    asm("mul.rn.f32x2 %0, %1, %2;" : "=l"(d) : "l"(a), "l"(b));
    return d;
}
static __device__ __forceinline__ ull add2(ull a, ull b) {
    ull d;
    asm("add.rn.f32x2 %0, %1, %2;" : "=l"(d) : "l"(a), "l"(b));
    return d;
}

static __device__ __forceinline__ float hsum16(const ull* y) {
    ull t8[8];
#pragma unroll
    for (int i = 0; i < 8; i++) t8[i] = add2(y[2 * i], y[2 * i + 1]);
    ull a = add2(t8[0], t8[1]);
    ull b = add2(t8[2], t8[3]);
    ull c = add2(t8[4], t8[5]);
    ull d = add2(t8[6], t8[7]);
    ull e = add2(a, b);
    ull f = add2(c, d);
    ull g = add2(e, f);
    float lo, hi; upk2(lo, hi, g);
    return lo + hi;
}

static __device__ __forceinline__ float gelu_erf(float v) {
    return 0.5f * v * (1.0f + erff(v * 0.70710678118654752440f));
}

// =====================================================================
// K0: derive per-(h,n) recurrence coefficients (double precision; tiny)
//   w = exp(dt*A); C' = (Cr+iCi)*(w-1)/A
//   y[t] = a*y[t-1] + b*y[t-2] + p*u[t] + q*u[t-1]
//   a=2Re(w), b=-|w|^2, p=2Re(C'), q=-2Re(conj(w)*C')
//   s_t: homogeneous propagator (s_0=1, s_{-1}=0), need s_T, s_{T-1}, s_{T-2}
// =====================================================================
__global__ void k_setup(const float* __restrict__ log_dt,
                        const float* __restrict__ A_real,
                        const float* __restrict__ A_imag,
                        const float* __restrict__ C_real,
                        const float* __restrict__ C_imag) {
    int i = blockIdx.x * blockDim.x + threadIdx.x;
    if (i >= Hn * Nn) return;
    int h = i / Nn;
    int n = i % Nn;

    double dt = exp((double)log_dt[h]);
    double Ar = -exp((double)A_real[i]);
    double Ai = (double)A_imag[i];
    double ar = Ar * dt, ai = Ai * dt;
    double er = exp(ar);
    double wr = er * cos(ai), wi = er * sin(ai);

    double den = Ar * Ar + Ai * Ai;
    double e1r = wr - 1.0, e1i = wi;
    double qr = (e1r * Ar + e1i * Ai) / den;
    double qi = (e1i * Ar - e1r * Ai) / den;
    double Crv = (double)C_real[i], Civ = (double)C_imag[i];
    double cr = Crv * qr - Civ * qi;
    double ci = Crv * qi + Civ * qr;

    double alpha = 2.0 * wr;
    double beta  = -(wr * wr + wi * wi);
    double p = 2.0 * cr;
    double q = -2.0 * (wr * cr + wi * ci);

    int m = n >> 1, lane = n & 1;
    float* ab = (float*)g_ab;
    float* pq = (float*)g_pq;
    int bidx = (h * NP + m) * 4;
    ab[bidx + lane]     = (float)alpha;
    ab[bidx + 2 + lane] = (float)beta;
    pq[bidx + lane]     = (float)p;
    pq[bidx + 2 + lane] = (float)q;

    // homogeneous propagator via the recurrence itself (stable, no division)
    float af = (float)alpha, bf = (float)beta;
    float x3 = 0.f;          // s_{t-2}
    float x2 = 0.f;          // s_{t-1}  (s_{-1}=0)
    float x1 = 1.f;          // s_t      (s_0 = 1)
    for (int t = 1; t <= Tn; ++t) {
        float x0 = af * x1 + bf * x2;
        x3 = x2; x2 = x1; x1 = x0;
    }
    // x1 = s_T, x2 = s_{T-1}, x3 = s_{T-2}
    g_S[i] = make_float4(x1, bf * x2, x2, bf * x3);
}

// =====================================================================
// Pass A: chunk-local scan with zero ICs -> end states (y[T-1], y[T-2])
// thread = (b, h, c); lanes = consecutive h -> coalesced u loads
// =====================================================================
__global__ void __launch_bounds__(256, 1)
k_passA(const float* __restrict__ u) {
    int gid = blockIdx.x * 256 + threadIdx.x;
    int lane = gid & 31;
    int r = gid >> 5;
    int hh = r & 31;            // H/32 = 32 tiles
    int bc = r >> 5;            // 0..B*C-1
    int h = hh * 32 + lane;
    int b = bc >> 4;            // /Cn
    int c = bc & 15;

    ull ap[NP], bp[NP], pp[NP], qp[NP];
    const ulonglong2* A2 = reinterpret_cast<const ulonglong2*>(g_ab) + h * NP;
    const ulonglong2* P2 = reinterpret_cast<const ulonglong2*>(g_pq) + h * NP;
#pragma unroll
    for (int m = 0; m < NP; m++) {
        ulonglong2 v = A2[m]; ap[m] = v.x; bp[m] = v.y;
        ulonglong2 w = P2[m]; pp[m] = w.x; qp[m] = w.y;
    }

    ull y1[NP], y2[NP];
#pragma unroll
    for (int m = 0; m < NP; m++) { y1[m] = 0ull; y2[m] = 0ull; }

    size_t base = ((size_t)(b * Ln + c * Tn)) * Hn + h;
    const float* up = u + base;

    float um = (c > 0) ? up[-Hn] : 0.f;
    ull uprev = pk2(um, um);
    float unext = up[0];

    for (int t = 0; t < Tn; t += 2) {
        float ua = unext;
        float ub = up[Hn];
        unext = (t + 2 < Tn) ? up[2 * Hn] : 0.f;

        ull uc = pk2(ua, ua);
#pragma unroll
        for (int m = 0; m < NP; m++) {
            ull tm = mul2(qp[m], uprev);
            tm = fma2(pp[m], uc, tm);
            tm = fma2(bp[m], y2[m], tm);
            y2[m] = fma2(ap[m], y1[m], tm);     // y2 = y[t]
        }
        ull un = pk2(ub, ub);
#pragma unroll
        for (int m = 0; m < NP; m++) {
            ull tm = mul2(qp[m], uc);
            tm = fma2(pp[m], un, tm);
            tm = fma2(bp[m], y1[m], tm);
            y1[m] = fma2(ap[m], y2[m], tm);     // y1 = y[t+1]
        }
        uprev = un;
        up += 2 * Hn;
    }
    // y1 = y[T-1], y2 = y[T-2]
    float4* st = g_state + ((size_t)((b * Hn + h) * Cn + c)) * NP;
#pragma unroll
    for (int m = 0; m < NP; m++) {
        float a_lo, a_hi, b_lo, b_hi;
        upk2(a_lo, a_hi, y1[m]);
        upk2(b_lo, b_hi, y2[m]);
        st[m] = make_float4(a_lo, b_lo, a_hi, b_hi);
    }
}

// =====================================================================
// Pass B: sequential combine over chunks (C=16 steps); converts local end
// states into carry-in ICs stored back in-place.
// thread = (b, h, n); lanes = consecutive n -> coalesced
// =====================================================================
__global__ void k_passB() {
    int gid = blockIdx.x * blockDim.x + threadIdx.x;   // B*H*N threads
    int n = gid & (Nn - 1);
    int h = (gid >> 5) & (Hn - 1);
    int b = gid >> 15;

    float4 s = g_S[h * Nn + n];
    float Y1 = 0.f, Y2 = 0.f;

    float2* g2 = reinterpret_cast<float2*>(g_state);
    size_t base = ((size_t)(b * Hn + h)) * Cn * Nn + n;
    for (int c = 0; c < Cn; c++) {
        size_t idx = base + (size_t)c * Nn;
        float2 Lv = g2[idx];
        g2[idx] = make_float2(Y1, Y2);                 // carry-in for chunk c
        float nY1 = Lv.x + s.x * Y1 + s.y * Y2;        // y[cT+T-1]
        float nY2 = Lv.y + s.z * Y1 + s.w * Y2;        // y[cT+T-2]
        Y1 = nY1; Y2 = nY2;
    }
}

// =====================================================================
// Pass C: re-scan each chunk from true carry-in, reduce over 32 modes,
// + D*u, erf-GELU, write output. Same layout as Pass A.
// =====================================================================
__global__ void __launch_bounds__(256, 1)
k_passC(const float* __restrict__ u, const float* __restrict__ Dp,
        float* __restrict__ out) {
    int gid = blockIdx.x * 256 + threadIdx.x;
    int lane = gid & 31;
    int r = gid >> 5;
    int hh = r & 31;
    int bc = r >> 5;
    int h = hh * 32 + lane;
    int b = bc >> 4;
    int c = bc & 15;

    ull ap[NP], bp[NP], pp[NP], qp[NP];
    const ulonglong2* A2 = reinterpret_cast<const ulonglong2*>(g_ab) + h * NP;
    const ulonglong2* P2 = reinterpret_cast<const ulonglong2*>(g_pq) + h * NP;
#pragma unroll
    for (int m = 0; m < NP; m++) {
        ulonglong2 v = A2[m]; ap[m] = v.x; bp[m] = v.y;
        ulonglong2 w = P2[m]; pp[m] = w.x; qp[m] = w.y;
    }

    ull y1[NP], y2[NP];
    const float4* st = g_state + ((size_t)((b * Hn + h) * Cn + c)) * NP;
#pragma unroll
    for (int m = 0; m < NP; m++) {
        float4 v = st[m];
        y1[m] = pk2(v.x, v.z);   // y[-1] per mode pair
        y2[m] = pk2(v.y, v.w);   // y[-2]
    }

    float Dv = *Dp;

    size_t base = ((size_t)(b * Ln + c * Tn)) * Hn + h;
    const float* up = u + base;
    float* op = out + base;

    float um = (c > 0) ? up[-Hn] : 0.f;
    ull uprev = pk2(um, um);
    float unext = up[0];

    for (int t = 0; t < Tn; t += 2) {
        float ua = unext;
        float ub = up[Hn];
        unext = (t + 2 < Tn) ? up[2 * Hn] : 0.f;

        ull uc = pk2(ua, ua);
#pragma unroll
        for (int m = 0; m < NP; m++) {
            ull tm = mul2(qp[m], uprev);
            tm = fma2(pp[m], uc, tm);
            tm = fma2(bp[m], y2[m], tm);
            y2[m] = fma2(ap[m], y1[m], tm);     // newest = y[t]
        }
        {
            float acc = hsum16(y2);
            float vv = fmaf(Dv, ua, acc);
            op[0] = gelu_erf(vv);
        }

        ull un = pk2(ub, ub);
#pragma unroll
        for (int m = 0; m < NP; m++) {
            ull tm = mul2(qp[m], uc);
            tm = fma2(pp[m], un, tm);
            tm = fma2(bp[m], y1[m], tm);
            y1[m] = fma2(ap[m], y2[m], tm);     // newest = y[t+1]
        }
        {
            float acc = hsum16(y1);
            float vv = fmaf(Dv, ub, acc);
            op[Hn] = gelu_erf(vv);
        }

        uprev = un;
        up += 2 * Hn;
        op += 2 * Hn;
    }
}

// =====================================================================
// launch
// =====================================================================
extern "C" void kernel_launch(void* const* d_in, const int* in_sizes, int n_in,
                              void* d_out, int out_size) {
    (void)in_sizes; (void)n_in; (void)out_size;
    const float* u      = (const float*)d_in[0];
    const float* log_dt = (const float*)d_in[1];
    const float* A_real = (const float*)d_in[2];
    const float* A_imag = (const float*)d_in[3];
    const float* C_real = (const float*)d_in[4];
    const float* C_imag = (const float*)d_in[5];
    const float* D      = (const float*)d_in[6];
    float* out = (float*)d_out;

    k_setup<<<(Hn * Nn + 255) / 256, 256>>>(log_dt, A_real, A_imag, C_real, C_imag);
    k_passA<<<(Bn * Hn * Cn) / 256, 256>>>(u);
    k_passB<<<(Bn * Hn * Nn) / 256, 256>>>();
    k_passC<<<(Bn * Hn * Cn) / 256, 256>>>(u, D, out);
}